// round 17
// baseline (speedup 1.0000x reference)
#include <cuda_runtime.h>
#include <cuda_fp16.h>
#include <cstdint>

#define BSZ    16384
#define QKV_LD 768
#define NROWS  (BSZ*3)
#define LN_EPS 1e-6f
#define TEMP_INV 0.17677669529663687f
#define APAD   3072      // A layout stride; used cols = 2048+512+448 = 3008

// ---------------- scratch (static device arrays; no cudaMalloc) --------------
__device__ __align__(16) __half g_qh [BSZ*QKV_LD];
__device__ __align__(16) __half g_kh [BSZ*QKV_LD];
__device__ __align__(16) __half g_vh [BSZ*QKV_LD];
__device__ __align__(16) __half g_fco[BSZ*QKV_LD];
__device__ __align__(16) __half g_ah[(size_t)BSZ*APAD];
__device__ __align__(16) __half g_wh[(size_t)3*256*APAD];
__device__ __align__(16) __half g_oh[(size_t)NROWS*256];
__device__ __align__(16) __half g_fch[256*256];

// ---------------- small helpers ----------------------------------------------
__device__ __forceinline__ uint32_t su32(const void* p) {
    return (uint32_t)__cvta_generic_to_shared(p);
}
__device__ __forceinline__ void cp16(uint32_t dst, const void* src) {
    asm volatile("cp.async.cg.shared.global [%0], [%1], 16;"
                 :: "r"(dst), "l"(src) : "memory");
}
__device__ __forceinline__ void cp_commit() {
    asm volatile("cp.async.commit_group;" ::: "memory");
}
__device__ __forceinline__ void ldm_x4(uint32_t& r0, uint32_t& r1, uint32_t& r2,
                                       uint32_t& r3, uint32_t addr) {
    asm volatile("ldmatrix.sync.aligned.m8n8.x4.shared.b16 {%0,%1,%2,%3}, [%4];"
                 : "=r"(r0), "=r"(r1), "=r"(r2), "=r"(r3) : "r"(addr));
}
__device__ __forceinline__ void mma_f16(float* c, uint32_t a0, uint32_t a1,
                                        uint32_t a2, uint32_t a3,
                                        uint32_t b0, uint32_t b1) {
    asm volatile(
        "mma.sync.aligned.m16n8k16.row.col.f32.f16.f16.f32 "
        "{%0,%1,%2,%3}, {%4,%5,%6,%7}, {%8,%9}, {%0,%1,%2,%3};"
        : "+f"(c[0]), "+f"(c[1]), "+f"(c[2]), "+f"(c[3])
        : "r"(a0), "r"(a1), "r"(a2), "r"(a3), "r"(b0), "r"(b1));
}
__device__ __forceinline__ float dot8s(const __half* a, const __half* b) {
    const __half2* pa = (const __half2*)a;
    const __half2* pb = (const __half2*)b;
    float s = 0.f;
#pragma unroll
    for (int i = 0; i < 4; i++) {
        float2 fa = __half22float2(pa[i]), fb = __half22float2(pb[i]);
        s = fmaf(fa.x, fb.x, s);
        s = fmaf(fa.y, fb.y, s);
    }
    return s;
}

// ---------------- conv_x: X fp32 -> padded fp16 A ------------------------------
__device__ __forceinline__ float4 load_seg(const float* __restrict__ X, int row, int col) {
    float4 v = make_float4(0.f, 0.f, 0.f, 0.f);
    if (col < 2048)      { if (col < 2000) v = *(const float4*)(X + (size_t)row*2900 + col); }
    else if (col < 2560) { int c = col-2048; if (c < 500) v = *(const float4*)(X + (size_t)row*2900 + 2000 + c); }
    else if (col < 3008) { int c = col-2560; if (c < 400) v = *(const float4*)(X + (size_t)row*2900 + 2500 + c); }
    return v;
}
__global__ void __launch_bounds__(256) conv_x_kernel(const float* __restrict__ X)
{
    int col = (blockIdx.x * 256 + threadIdx.x) * 8;
    if (col >= 3008) return;
    int row = blockIdx.y;

    float4 v0 = load_seg(X, row, col);
    float4 v1 = load_seg(X, row, col + 4);

    uint4 pk;
    __half2* ph = (__half2*)&pk;
    ph[0].x = __float2half(v0.x); ph[0].y = __float2half(v0.y);
    ph[1].x = __float2half(v0.z); ph[1].y = __float2half(v0.w);
    ph[2].x = __float2half(v1.x); ph[2].y = __float2half(v1.y);
    ph[3].x = __float2half(v1.z); ph[3].y = __float2half(v1.w);
    *(uint4*)&g_ah[(size_t)row*APAD + col] = pk;
}

// ---------------- conv_wt: tiled transpose of all weights ----------------------
#define NWT_BLOCKS 580    // 3*(128+32+28) + 16
struct WA { const float* w[9]; const float* fcw; };

__global__ void __launch_bounds__(256) conv_wt_kernel(WA a)
{
    const int KpT[10]  = {2048,512,448, 2048,512,448, 2048,512,448, 256};
    const int KmT[10]  = {2000,500,400, 2000,500,400, 2000,500,400, 256};
    const int offT[10] = {0,2048,2560, 0,2048,2560, 0,2048,2560, 0};

    int b = blockIdx.x;
    int seg = 0, base = 0;
#pragma unroll
    for (int s = 0; s < 10; s++) {
        int nt = KpT[s] >> 4;
        if (b < base + nt) { seg = s; break; }
        base += nt;
    }
    int lt = b - base;
    int ktiles = KpT[seg] >> 6;
    int kp0 = (lt % ktiles) * 64;
    int n0  = (lt / ktiles) * 64;
    int Km  = KmT[seg];
    const float* W = (seg < 9) ? a.w[seg] : a.fcw;
    __half* dst; int ld, coff;
    if (seg < 9) { dst = g_wh + (size_t)(seg / 3) * 256 * APAD; ld = APAD; coff = offT[seg]; }
    else         { dst = g_fch; ld = 256; coff = 0; }

    __shared__ float s[64][65];
    int tid = threadIdx.x;
    int c = tid & 63, r0 = tid >> 6;
#pragma unroll
    for (int i = 0; i < 16; i++) {
        int r = r0 + i * 4;
        int kp = kp0 + r;
        s[r][c] = (kp < Km) ? W[(size_t)kp * 256 + n0 + c] : 0.f;
    }
    __syncthreads();

    int kl = (tid & 31) * 2;
#pragma unroll
    for (int j = 0; j < 8; j++) {
        int nl = (tid >> 5) + j * 8;
        __half2 h;
        h.x = __float2half(s[kl][nl]);
        h.y = __float2half(s[kl + 1][nl]);
        *(__half2*)&dst[(size_t)(n0 + nl) * ld + coff + kp0 + kl] = h;
    }
}

// ---------------- mma.sync fp16 GEMM -------------------------------------------
struct GP {
    const __half *Ah, *B;
    int ldA, ldB, colA, colB, Kp;
    const float* bias;
    __half* C; int ldc;
};

#define SOFF_B 18432
#define SSTG   36864
#define NSTAGE 3
#define SMEM_GEMM (NSTAGE*SSTG)   // 110592 -> 2 CTAs/SM

__device__ __forceinline__ void gemm_body(const GP p)
{
    extern __shared__ __align__(16) char dsm[];
    const int tid  = threadIdx.x;
    const int lane = tid & 31, wid = tid >> 5;
    const int wm = wid >> 2, wn = wid & 3;
    const int row0 = blockIdx.y * 128, col0 = blockIdx.x * 128;
    const uint32_t sbase = su32(dsm);

    const int nchunk = p.Kp >> 6;

    auto load_chunk = [&](int c, int buf) {
        const __half* As = p.Ah + (size_t)row0 * p.ldA + p.colA + c * 64;
        const __half* Bs = p.B  + (size_t)col0 * p.ldB + p.colB + c * 64;
        uint32_t Sd = sbase + buf * SSTG;
#pragma unroll
        for (int i = 0; i < 4; i++) {
            int id = i * 256 + tid, r = id >> 3, kg = id & 7;
            cp16(Sd + r * 144 + kg * 16, As + (size_t)r * p.ldA + kg * 8);
            cp16(Sd + SOFF_B + r * 144 + kg * 16, Bs + (size_t)r * p.ldB + kg * 8);
        }
    };

    float acc[4][4][4];
#pragma unroll
    for (int i = 0; i < 4; i++)
#pragma unroll
        for (int j = 0; j < 4; j++)
#pragma unroll
            for (int r = 0; r < 4; r++) acc[i][j][r] = 0.f;

    load_chunk(0, 0); cp_commit();

    const uint32_t a_off = (uint32_t)((wm * 64 + (lane & 15)) * 144 + ((lane >> 4) << 4));
    const uint32_t b_off = (uint32_t)((wn * 32 + (lane & 7) + ((lane & 16) >> 1)) * 144
                                      + ((lane & 8) << 1));

    int bufc = 0;
    for (int c = 0; c < nchunk; c++) {
        int bnew = bufc + 1; if (bnew == NSTAGE) bnew = 0;
        if (c + 1 < nchunk) {
            load_chunk(c + 1, bnew); cp_commit();
            asm volatile("cp.async.wait_group 1;" ::: "memory");
        } else {
            asm volatile("cp.async.wait_group 0;" ::: "memory");
        }
        __syncthreads();

        const uint32_t Sd = sbase + bufc * SSTG;
        const uint32_t Ab = Sd + a_off;
        const uint32_t Bb = Sd + SOFF_B + b_off;
#pragma unroll
        for (int kstep = 0; kstep < 4; kstep++) {
            const uint32_t kk = kstep * 32;
            uint32_t a[4][4], b[2][4];
#pragma unroll
            for (int mt = 0; mt < 4; mt++)
                ldm_x4(a[mt][0], a[mt][1], a[mt][2], a[mt][3],
                       Ab + mt * (16 * 144) + kk);
#pragma unroll
            for (int ng = 0; ng < 2; ng++)
                ldm_x4(b[ng][0], b[ng][1], b[ng][2], b[ng][3],
                       Bb + ng * (16 * 144) + kk);
#pragma unroll
            for (int mt = 0; mt < 4; mt++)
#pragma unroll
                for (int nt = 0; nt < 4; nt++)
                    mma_f16(acc[mt][nt],
                            a[mt][0], a[mt][1], a[mt][2], a[mt][3],
                            b[nt >> 1][(nt & 1) * 2], b[nt >> 1][(nt & 1) * 2 + 1]);
        }
        bufc = bnew;
    }

    const int grp = lane >> 2, tig = lane & 3;
#pragma unroll
    for (int mt = 0; mt < 4; mt++) {
        int r = row0 + wm * 64 + mt * 16 + grp;
#pragma unroll
        for (int nt = 0; nt < 4; nt++) {
            int col = col0 + wn * 32 + nt * 8 + tig * 2;
            float b0 = p.bias[col], b1 = p.bias[col + 1];
            __half2 lo, hi;
            lo.x = __float2half(acc[mt][nt][0] + b0);
            lo.y = __float2half(acc[mt][nt][1] + b1);
            hi.x = __float2half(acc[mt][nt][2] + b0);
            hi.y = __float2half(acc[mt][nt][3] + b1);
            *(__half2*)(p.C + (size_t)r * p.ldc + col) = lo;
            *(__half2*)(p.C + (size_t)(r + 8) * p.ldc + col) = hi;
        }
    }
}

struct B9 { const float* b[9]; };

__global__ void __launch_bounds__(256, 2) qkv_gemm_kernel(B9 biases)
{
    const int colA[3] = {0, 2048, 2560};
    const int Kp[3]   = {2048, 512, 448};
    int z = blockIdx.z, m = z / 3, t = z - m * 3;
    GP p;
    p.Ah = g_ah; p.ldA = APAD; p.colA = colA[m];
    p.B  = g_wh + (size_t)t * 256 * APAD;
    p.ldB = APAD; p.colB = colA[m];
    p.Kp = Kp[m];
    p.bias = biases.b[t * 3 + m];
    p.C = ((t == 0) ? g_qh : (t == 1) ? g_kh : g_vh) + m * 256;
    p.ldc = QKV_LD;
    gemm_body(p);
}

__global__ void __launch_bounds__(256, 2) fc_gemm_kernel(const float* fc_b)
{
    GP p;
    p.Ah = g_oh; p.ldA = 256; p.colA = 0;
    p.B  = g_fch; p.ldB = 256; p.colB = 0;
    p.Kp = 256;
    p.bias = fc_b; p.C = g_fco; p.ldc = 256;
    gemm_body(p);
}

// ------------- fused attention, smem-staged (32 samples / 256-thread block) ----
// Identity: (a/G)/max(sum|a/G|,1e-12) == a/sum|a|  (global-min G cancels).
// q/k/v staged via coalesced cp.async; o assembled in (dead) q region.
#define ATTN_SMP   32
#define ATTN_BYTES (ATTN_SMP*768*2)        // 49152 per tensor
#define SMEM_ATTN  (3*ATTN_BYTES)          // 147456

__global__ void __launch_bounds__(256) attn_fused_kernel()
{
    extern __shared__ __align__(16) char asm_[];
    __half* sq = (__half*)asm_;                        // q, later o
    __half* sk = (__half*)(asm_ + ATTN_BYTES);
    __half* sv = (__half*)(asm_ + 2 * ATTN_BYTES);

    const int tid = threadIdx.x;
    const size_t s0off = (size_t)blockIdx.x * ATTN_SMP * 768;
    const uint32_t sb = su32(asm_);

    // coalesced staging: 3 x 49152B, 16B per cp.async
#pragma unroll
    for (int i = 0; i < ATTN_BYTES / (256 * 16); i++) {
        uint32_t off = (uint32_t)(tid * 16 + i * 4096);
        cp16(sb + off,                  (const char*)(g_qh + s0off) + off);
        cp16(sb + ATTN_BYTES + off,     (const char*)(g_kh + s0off) + off);
        cp16(sb + 2 * ATTN_BYTES + off, (const char*)(g_vh + s0off) + off);
    }
    cp_commit();
    asm volatile("cp.async.wait_group 0;" ::: "memory");
    __syncthreads();

    // one (sample, head) unit per thread
    const int sl = tid >> 3, h = tid & 7;
    const int ubase = sl * 768 + h * 32;   // halves offset of head block

    float p[3][3];
#pragma unroll
    for (int m = 0; m < 3; m++) {
        const __half* qm = sq + ubase + m * 256;
        float a[3];
#pragma unroll
        for (int n = 0; n < 3; n++) {
            const __half* kn = sk + ubase + n * 256;
            float s = 0.f;
#pragma unroll
            for (int j = 0; j < 4; j++) s += dot8s(qm + j * 8, kn + j * 8);
            a[n] = s * TEMP_INV;
        }
        float l1 = fmaxf(fabsf(a[0]) + fabsf(a[1]) + fabsf(a[2]), 1e-30f);
        float r0 = a[0]/l1, r1 = a[1]/l1, r2 = a[2]/l1;
        float mx = fmaxf(r0, fmaxf(r1, r2));
        float e0 = expf(r0-mx), e1 = expf(r1-mx), e2 = expf(r2-mx);
        float es = e0 + e1 + e2;
        p[m][0] = e0/es; p[m][1] = e1/es; p[m][2] = e2/es;
    }
    __syncthreads();   // q,k fully consumed -> sq reusable for o

    // PV: o[m] = sum_n p[m][n] * v[n]; write into sq
#pragma unroll
    for (int j = 0; j < 4; j++) {
        const __half2* v0 = (const __half2*)(sv + ubase + 0*256 + j*8);
        const __half2* v1 = (const __half2*)(sv + ubase + 1*256 + j*8);
        const __half2* v2 = (const __half2*)(sv + ubase + 2*256 + j*8);
        float2 f0[4], f1[4], f2[4];
#pragma unroll
        for (int i = 0; i < 4; i++) {
            f0[i] = __half22float2(v0[i]);
            f1[i] = __half22float2(v1[i]);
            f2[i] = __half22float2(v2[i]);
        }
#pragma unroll
        for (int m = 0; m < 3; m++) {
            __half2* om = (__half2*)(sq + ubase + m * 256 + j * 8);
#pragma unroll
            for (int i = 0; i < 4; i++) {
                __half2 r;
                r.x = __float2half(p[m][0]*f0[i].x + p[m][1]*f1[i].x + p[m][2]*f2[i].x);
                r.y = __float2half(p[m][0]*f0[i].y + p[m][1]*f1[i].y + p[m][2]*f2[i].y);
                om[i] = r;
            }
        }
    }
    __syncthreads();

    // coalesced store of o
    const uint4* so = (const uint4*)sq;
    uint4* go = (uint4*)(g_oh + s0off);
#pragma unroll
    for (int i = 0; i < ATTN_BYTES / (256 * 16); i++)
        go[tid + i * 256] = so[tid + i * 256];
}

// ------------- fused residual + LN + out GEMM (8 samples/block, smem weights) --
__global__ void __launch_bounds__(256) ln_out_kernel(
    const float* __restrict__ ln_g, const float* __restrict__ ln_b,
    const float* __restrict__ out_w, const float* __restrict__ out_b,
    float* __restrict__ out)
{
    __shared__ float sw[768 * 5];
    __shared__ float sg[256], sb[256];

    int tid = threadIdx.x;
    for (int i = tid; i < 768 * 5; i += 256) sw[i] = out_w[i];
    if (tid < 256) { sg[tid] = ln_g[tid]; sb[tid] = ln_b[tid]; }
    __syncthreads();

    int lane = tid & 31, wid = tid >> 5;
    int s = blockIdx.x * 8 + wid;

    float x[3][8];
#pragma unroll
    for (int m = 0; m < 3; m++) {
        size_t base = (size_t)(s * 3 + m) * 256;
#pragma unroll
        for (int i = 0; i < 8; i++) {
            int col = i * 32 + lane;
            x[m][i] = __half2float(g_fco[base + col]) + __half2float(g_vh[base + col]);
        }
    }

    float mu[3], rstd[3];
#pragma unroll
    for (int m = 0; m < 3; m++) {
        float s1 = 0.f, s2 = 0.f;
#pragma unroll
        for (int i = 0; i < 8; i++) { s1 += x[m][i]; s2 = fmaf(x[m][i], x[m][i], s2); }
#pragma unroll
        for (int off = 16; off; off >>= 1) {
            s1 += __shfl_xor_sync(0xFFFFFFFFu, s1, off);
            s2 += __shfl_xor_sync(0xFFFFFFFFu, s2, off);
        }
        mu[m] = s1 * (1.0f / 256.0f);
        float var = s2 * (1.0f / 256.0f) - mu[m] * mu[m];
        rstd[m] = rsqrtf(var + LN_EPS);
    }

    float acc[5] = {0.f, 0.f, 0.f, 0.f, 0.f};
#pragma unroll
    for (int m = 0; m < 3; m++) {
#pragma unroll
        for (int i = 0; i < 8; i++) {
            int col = i * 32 + lane;
            float xn = (x[m][i] - mu[m]) * rstd[m] * sg[col] + sb[col];
            const float* wr = &sw[(m * 256 + col) * 5];
#pragma unroll
            for (int c = 0; c < 5; c++) acc[c] = fmaf(xn, wr[c], acc[c]);
        }
    }
#pragma unroll
    for (int off = 16; off; off >>= 1)
#pragma unroll
        for (int c = 0; c < 5; c++)
            acc[c] += __shfl_xor_sync(0xFFFFFFFFu, acc[c], off);
    if (lane < 5) out[s * 5 + lane] = acc[lane] + out_b[lane];
}

// ==============================================================================
extern "C" void kernel_launch(void* const* d_in, const int* in_sizes, int n_in,
                              void* d_out, int out_size)
{
    const float* X = (const float*)d_in[0];
    WA wa; B9 bs;
    for (int t = 0; t < 3; t++)
        for (int m = 0; m < 3; m++) {
            wa.w[t*3+m] = (const float*)d_in[1 + t*6 + m*2];
            bs.b[t*3+m] = (const float*)d_in[2 + t*6 + m*2];
        }
    wa.fcw = (const float*)d_in[19];
    const float* fc_b  = (const float*)d_in[20];
    const float* ln_g  = (const float*)d_in[21];
    const float* ln_b  = (const float*)d_in[22];
    const float* out_w = (const float*)d_in[23];
    const float* out_b = (const float*)d_in[24];
    float* out = (float*)d_out;

    static int smem_set = 0;
    if (!smem_set) {
        cudaFuncSetAttribute(qkv_gemm_kernel,  cudaFuncAttributeMaxDynamicSharedMemorySize, SMEM_GEMM);
        cudaFuncSetAttribute(fc_gemm_kernel,   cudaFuncAttributeMaxDynamicSharedMemorySize, SMEM_GEMM);
        cudaFuncSetAttribute(attn_fused_kernel, cudaFuncAttributeMaxDynamicSharedMemorySize, SMEM_ATTN);
        smem_set = 1;
    }

    conv_x_kernel<<<dim3(2, BSZ), 256>>>(X);        // idx 0
    conv_wt_kernel<<<NWT_BLOCKS, 256>>>(wa);        // idx 1

    qkv_gemm_kernel<<<dim3(2, BSZ/128, 9), 256, SMEM_GEMM>>>(bs);  // idx 2

    attn_fused_kernel<<<BSZ/ATTN_SMP, 256, SMEM_ATTN>>>();         // idx 3 -> ncu target

    fc_gemm_kernel<<<dim3(2, NROWS/128, 1), 256, SMEM_GEMM>>>(fc_b);

    ln_out_kernel<<<BSZ/8, 256>>>(ln_g, ln_b, out_w, out_b, out);
}